// round 8
// baseline (speedup 1.0000x reference)
#include <cuda_runtime.h>
#include <stdint.h>

// Hash-grid trilinear interpolation — two-pass table slicing, thread = point.
//
// DRAM traffic: pass P gathers only corners in table slice P (top vid bit,
// 64MB/slice). Slice fits L2 during its pass -> bucket reuse captured by LRU
// (confirmed R6/R7: ~260MB/pass vs 628MB unsliced). Pass 0 writes partial
// sums to out; pass 1 adds and finalizes.
//
// Latency: R7 showed the (pt,half) layout leaves DRAM at 62% (MLP ~4).
// Thread-per-point issues 16 predicated LDG.128 back-to-back (~8 active,
// MLP ~8-16) — the shape that sustained 5.7TB/s in R1.

#define BUCKETS_MASK ((1u << 22) - 1u)
#define SLICE_SHIFT 21
#define P1 1u
#define P2 2654435761u
#define P3 805459861u

template <int PASS>
__global__ void __launch_bounds__(256) hashgrid_pt_kernel(
    const float* __restrict__ pts,   // (N,3)
    const char*  __restrict__ vf,    // (BUCKETS, 8 fp32) = 32 B per bucket
    float4*      __restrict__ out,   // (N, 8 fp32) = 2 float4 per point
    int n)
{
    int i = blockIdx.x * blockDim.x + threadIdx.x;
    if (i >= n) return;

    float x = pts[3 * i + 0];
    float y = pts[3 * i + 1];
    float z = pts[3 * i + 2];

    float qx = x * 1024.0f, qy = y * 1024.0f, qz = z * 1024.0f;
    float bxf = floorf(qx), byf = floorf(qy), bzf = floorf(qz);
    float fx = qx - bxf, fy = qy - byf, fz = qz - bzf;

    uint32_t bx = (uint32_t)(int)bxf;
    uint32_t by = (uint32_t)(int)byf;
    uint32_t bz = (uint32_t)(int)bzf;
    uint32_t h  = bx * P1 + by * P2 + bz * P3;

    uint32_t vid[8];
    vid[0] = (h)                & BUCKETS_MASK;
    vid[1] = (h + P1)           & BUCKETS_MASK;
    vid[2] = (h + P2)           & BUCKETS_MASK;
    vid[3] = (h + P1 + P2)      & BUCKETS_MASK;
    vid[4] = (h + P3)           & BUCKETS_MASK;
    vid[5] = (h + P1 + P3)      & BUCKETS_MASK;
    vid[6] = (h + P2 + P3)      & BUCKETS_MASK;
    vid[7] = (h + P1 + P2 + P3) & BUCKETS_MASK;

    float gx = 1.0f - fx, gy = 1.0f - fy, gz = 1.0f - fz;
    float w[8];
    w[0] = gx * gy * gz;  w[1] = fx * gy * gz;
    w[2] = gx * fy * gz;  w[3] = fx * fy * gz;
    w[4] = gx * gy * fz;  w[5] = fx * gy * fz;
    w[6] = gx * fy * fz;  w[7] = fx * fy * fz;

    // Issue all predicated gathers first — up to 16 LDG.128 in flight.
    float4 f0[8], f1[8];
#pragma unroll
    for (int c = 0; c < 8; c++) {
        bool active = ((vid[c] >> SLICE_SHIFT) == (uint32_t)PASS);
        f0[c] = make_float4(0.f, 0.f, 0.f, 0.f);
        f1[c] = make_float4(0.f, 0.f, 0.f, 0.f);
        if (active) {
            const float4* q = (const float4*)(vf + ((size_t)vid[c] << 5));
            f0[c] = __ldg(q);
            f1[c] = __ldg(q + 1);
        }
    }

    float4 a0 = make_float4(0.f, 0.f, 0.f, 0.f);
    float4 a1 = make_float4(0.f, 0.f, 0.f, 0.f);
#pragma unroll
    for (int c = 0; c < 8; c++) {
        float wc = w[c];
        a0.x = fmaf(wc, f0[c].x, a0.x);
        a0.y = fmaf(wc, f0[c].y, a0.y);
        a0.z = fmaf(wc, f0[c].z, a0.z);
        a0.w = fmaf(wc, f0[c].w, a0.w);
        a1.x = fmaf(wc, f1[c].x, a1.x);
        a1.y = fmaf(wc, f1[c].y, a1.y);
        a1.z = fmaf(wc, f1[c].z, a1.z);
        a1.w = fmaf(wc, f1[c].w, a1.w);
    }

    float4* op = out + 2 * (size_t)i;
    if (PASS == 0) {
        // plain stores: leave dirty lines in L2 for pass 1 to hit
        op[0] = a0;
        op[1] = a1;
    } else {
        float4 p0 = __ldcg(op);
        float4 p1 = __ldcg(op + 1);
        a0.x += p0.x; a0.y += p0.y; a0.z += p0.z; a0.w += p0.w;
        a1.x += p1.x; a1.y += p1.y; a1.z += p1.z; a1.w += p1.w;
        __stcs(op, a0);
        __stcs(op + 1, a1);
    }
}

extern "C" void kernel_launch(void* const* d_in, const int* in_sizes, int n_in,
                              void* d_out, int out_size)
{
    const float* pts = (const float*)d_in[0];
    const char*  vf  = (const char*)d_in[1];
    float4*      out = (float4*)d_out;

    int n = in_sizes[0] / 3;

    int block = 256;
    int grid = (n + block - 1) / block;

    hashgrid_pt_kernel<0><<<grid, block>>>(pts, vf, out, n);
    hashgrid_pt_kernel<1><<<grid, block>>>(pts, vf, out, n);
}